// round 5
// baseline (speedup 1.0000x reference)
#include <cuda_runtime.h>

#define Bn   16
#define Tn   262144
#define HOP  256
#define WINL 1024
#define PADL 384
#define Fn   1024          // Tn / HOP
#define Pn   22
#define NWARP 512          // total warps = sequences/32
#define SPAN  8960         // 32 frames * HOP + WINL - HOP = per-warp OLA span
#define STRIPL 768         // WINL - HOP = seam width

// Cross-warp seam partial sums (no allocation allowed in kernel_launch)
__device__ float d_strip_lo[NWARP][STRIPL];
__device__ float d_strip_hi[NWARP][STRIPL];

typedef unsigned long long ull;

static __device__ __forceinline__ ull pk2(float lo, float hi) {
    ull r; asm("mov.b64 %0,{%1,%2};" : "=l"(r) : "f"(lo), "f"(hi)); return r;
}
static __device__ __forceinline__ void upk2(float& lo, float& hi, ull v) {
    asm("mov.b64 {%0,%1},%2;" : "=f"(lo), "=f"(hi) : "l"(v));
}
static __device__ __forceinline__ ull fma2_(ull a, ull b, ull c) {
    ull r; asm("fma.rn.f32x2 %0,%1,%2,%3;" : "=l"(r) : "l"(a), "l"(b), "l"(c)); return r;
}
static __device__ __forceinline__ ull mul2_(ull a, ull b) {
    ull r; asm("mul.rn.f32x2 %0,%1,%2;" : "=l"(r) : "l"(a), "l"(b)); return r;
}
static __device__ __forceinline__ ull add2_(ull a, ull b) {
    ull r; asm("add.rn.f32x2 %0,%1,%2;" : "=l"(r) : "l"(a), "l"(b)); return r;
}

static __device__ __forceinline__ float hannf(int t) {
    return 0.5f - 0.5f * cosf(6.283185307179586f * (float)t * (1.0f / 1024.0f));
}

// smem layout (floats): acc[4][SPAN] | xs[4][32][34] | tile[4][32][34]
#define ACC_FLOATS  (4 * SPAN)
#define XS_FLOATS   (4 * 32 * 34)
#define SMEM_FLOATS (ACC_FLOATS + 2 * XS_FLOATS)
#define SMEM_BYTES  (SMEM_FLOATS * 4)

// ---------------------------------------------------------------------------
// Kernel 1: LPC synthesis (2-step blocked, packed f32x2) + windowed OLA into
//   per-warp smem accumulator. Interior written directly to out (norm==2);
//   768-sample seams written to strip buffers for kernel 2.
// ---------------------------------------------------------------------------
__global__ void __launch_bounds__(128, 1)
lpc_ola_kernel(const float* __restrict__ ex,
               const float* __restrict__ gain,
               const float* __restrict__ a,
               float* __restrict__ out) {
    extern __shared__ float smem[];

    const int warp = threadIdx.x >> 5;
    const int lane = threadIdx.x & 31;
    const int gw   = blockIdx.x * 4 + warp;   // 0..511
    const int s0   = gw * 32;                 // warp-base sequence index
    const int s    = s0 + lane;
    const int b    = s >> 10;                 // batch (Fn = 1024)
    const int ww   = gw & 31;                 // warp index within batch
    const int f0   = ww * 32;                 // warp-base frame

    float* __restrict__ acc  = smem + warp * SPAN;
    float* __restrict__ xsw  = smem + ACC_FLOATS + warp * 32 * 34;
    float* __restrict__ tlw  = smem + ACC_FLOATS + XS_FLOATS + warp * 32 * 34;

    // zero this warp's accumulator (2240 float4)
    #pragma unroll 4
    for (int i = lane; i < SPAN / 4; i += 32)
        ((float4*)acc)[i] = make_float4(0.f, 0.f, 0.f, 0.f);

    const float g = gain[s];

    // c[q] = -a[q-1] (q=1..22), c[23]=0 ; d[q] = c1*c[q] + c[q+1]
    float c[24];
    #pragma unroll
    for (int p = 0; p < Pn; ++p) c[p + 1] = -a[s * Pn + p];
    c[23] = 0.0f;
    const float c1  = c[1];
    const float c1g = c1 * g;

    ull CA[11], CB[11], H[11];
    #pragma unroll
    for (int k = 0; k < 11; ++k) {
        const float dlo = fmaf(c1, c[2 * k + 1], c[2 * k + 2]);
        const float dhi = fmaf(c1, c[2 * k + 2], c[2 * k + 3]);
        CA[k] = pk2(c[2 * k + 1], c[2 * k + 2]);
        CB[k] = pk2(dlo, dhi);
        H[k]  = 0ull;
    }

    const float* __restrict__ exb = ex + b * Tn;

    // prefetch chunk 0 (coalesced: lane sweeps time, r sweeps frames)
    float xr[32];
    #pragma unroll
    for (int r = 0; r < 32; ++r) {
        int idx = (f0 + r) * HOP + lane - PADL;
        xr[r] = ((unsigned)idx < (unsigned)Tn) ? exb[idx] : 0.0f;
    }

    for (int cchunk = 0; cchunk < 32; ++cchunk) {
        const int t0 = cchunk * 32;

        // commit prefetched chunk to smem
        #pragma unroll
        for (int r = 0; r < 32; ++r) xsw[r * 34 + lane] = xr[r];
        __syncwarp();

        // issue next chunk's global loads; latency hides under recurrence
        if (cchunk < 31) {
            const int t1 = t0 + 32;
            #pragma unroll
            for (int r = 0; r < 32; ++r) {
                int idx = (f0 + r) * HOP + t1 + lane - PADL;
                xr[r] = ((unsigned)idx < (unsigned)Tn) ? exb[idx] : 0.0f;
            }
        }

        // 16 blocks x 2 samples
        const float* xrow = xsw + lane * 34;
        float2 xp2 = *(const float2*)xrow;
        #pragma unroll
        for (int bk = 0; bk < 16; ++bk) {
            float2 xn2;
            if (bk < 15) xn2 = *(const float2*)(xrow + 2 * bk + 2);

            const float x0 = xp2.x, x1 = xp2.y;
            const float pre = c1g * x0;

            // A-chains (y0) first, H[0] last in each chain
            ull ae = mul2_(CA[10], H[10]);
            ae = fma2_(CA[8], H[8], ae);
            ae = fma2_(CA[6], H[6], ae);
            ae = fma2_(CA[4], H[4], ae);
            ae = fma2_(CA[2], H[2], ae);
            ull ao = mul2_(CA[9], H[9]);
            ao = fma2_(CA[7], H[7], ao);
            ao = fma2_(CA[5], H[5], ao);
            ao = fma2_(CA[3], H[3], ao);
            ao = fma2_(CA[1], H[1], ao);
            ae = fma2_(CA[0], H[0], ae);
            const ull accA = add2_(ae, ao);

            ull be = mul2_(CB[10], H[10]);
            be = fma2_(CB[8], H[8], be);
            be = fma2_(CB[6], H[6], be);
            be = fma2_(CB[4], H[4], be);
            be = fma2_(CB[2], H[2], be);
            ull bo = mul2_(CB[9], H[9]);
            bo = fma2_(CB[7], H[7], bo);
            bo = fma2_(CB[5], H[5], bo);
            bo = fma2_(CB[3], H[3], bo);
            bo = fma2_(CB[1], H[1], bo);
            be = fma2_(CB[0], H[0], be);
            const ull accB = add2_(be, bo);

            float aLo, aHi, bLo, bHi;
            upk2(aLo, aHi, accA);
            upk2(bLo, bHi, accB);

            const float y0 = fmaf(g, x0, aLo + aHi);
            const float y1 = fmaf(g, x1, (bLo + bHi) + pre);

            *(float2*)(tlw + lane * 34 + 2 * bk) = make_float2(y0, y1);

            #pragma unroll
            for (int k = 10; k > 0; --k) H[k] = H[k - 1];
            H[0] = pk2(y1, y0);

            xp2 = xn2;
        }
        __syncwarp();

        // windowed OLA accumulate: row r (frame f0+r) covers acc[r*256+t0 .. +32)
        const float wv = hannf(t0 + lane);
        #pragma unroll
        for (int r = 0; r < 32; ++r) {
            const int pos = r * HOP + t0 + lane;
            acc[pos] += tlw[r * 34 + lane] * wv;
        }
        __syncwarp();
    }

    // ---- emit results ----
    // interior [768, 8192): all 4 contributions local; norm == 2 exactly
    float* __restrict__ outb = out + (size_t)b * Tn + ww * 8192 + 384;
    const float4* __restrict__ acc4 = (const float4*)(acc + STRIPL);
    #pragma unroll 4
    for (int i = lane; i < (8192 - STRIPL) / 4; i += 32) {
        float4 v = acc4[i];
        v.x *= 0.5f; v.y *= 0.5f; v.z *= 0.5f; v.w *= 0.5f;
        ((float4*)outb)[i] = v;
    }
    // seams: partial sums for kernel 2
    #pragma unroll
    for (int j = lane; j < STRIPL; j += 32) {
        d_strip_lo[gw][j] = acc[j];
        d_strip_hi[gw][j] = acc[8192 + j];
    }
}

// ---------------------------------------------------------------------------
// Kernel 2: resolve seams. Region rg < 512: lower strip of warp rg (combined
//   with warp rg-1's upper strip when same batch). Regions 512..527: the final
//   warp of each batch's upper strip (all-local). Norm computed from hann.
// ---------------------------------------------------------------------------
__global__ void strip_kernel(float* __restrict__ out) {
    const int rg = blockIdx.x;
    const int j  = threadIdx.x;        // 0..767

    int w, pbase;                      // warp id, batch-local padded base
    float sum;
    if (rg < NWARP) {
        w = rg;
        const int ww = w & 31;
        pbase = ww * 8192;
        sum = d_strip_lo[w][j];
        if (ww > 0) sum += d_strip_hi[w - 1][j];
    } else {
        w = ((rg - NWARP) << 5) | 31;  // last warp of batch rg-512
        pbase = 31 * 8192 + 8192;      // = 262144
        sum = d_strip_hi[w][j];
    }
    const int b = w >> 5;
    const int p = pbase + j;           // batch-local padded coordinate
    const int o = p - PADL;
    if ((unsigned)o >= (unsigned)Tn) return;

    const int fhi = p >> 8;
    float norm = 0.0f;
    #pragma unroll
    for (int k = 0; k < 4; ++k) {
        const int ff = fhi - k;
        if (ff >= 0 && ff < Fn) norm += hannf(p - ff * HOP);
    }
    out[(size_t)b * Tn + o] = sum / norm;
}

// ---------------------------------------------------------------------------
extern "C" void kernel_launch(void* const* d_in, const int* in_sizes, int n_in,
                              void* d_out, int out_size) {
    const float* ex   = (const float*)d_in[0];
    const float* gain = (const float*)d_in[1];
    const float* a    = (const float*)d_in[2];
    float* out = (float*)d_out;

    cudaFuncSetAttribute(lpc_ola_kernel,
                         cudaFuncAttributeMaxDynamicSharedMemorySize, SMEM_BYTES);
    lpc_ola_kernel<<<128, 128, SMEM_BYTES>>>(ex, gain, a, out);
    strip_kernel<<<NWARP + Bn, STRIPL>>>(out);
}

// round 6
// speedup vs baseline: 1.1635x; 1.1635x over previous
#include <cuda_runtime.h>

#define Bn   16
#define Tn   262144
#define HOP  256
#define WINL 1024
#define PADL 384
#define Fn   1024
#define Pn   22
#define NGRP 512            // frame groups (32 frames each)
#define SPAN 8960           // per-group OLA span
#define STRIPL 768          // seam width
#define NCHUNK 20           // 640 samples / 32 per segment
#define SEGB_T0 384         // segB start time (256-sample warm-up)
#define WARM_CHUNKS 8       // segB chunks with t < 640 (discarded)

// Cross-group seam partial sums
__device__ float d_strip_lo[NGRP][STRIPL];
__device__ float d_strip_hi[NGRP][STRIPL];

typedef unsigned long long ull;

static __device__ __forceinline__ ull pk2(float lo, float hi) {
    ull r; asm("mov.b64 %0,{%1,%2};" : "=l"(r) : "f"(lo), "f"(hi)); return r;
}
static __device__ __forceinline__ void upk2(float& lo, float& hi, ull v) {
    asm("mov.b64 {%0,%1},%2;" : "=f"(lo), "=f"(hi) : "l"(v));
}
static __device__ __forceinline__ ull fma2_(ull a, ull b, ull c) {
    ull r; asm("fma.rn.f32x2 %0,%1,%2,%3;" : "=l"(r) : "l"(a), "l"(b), "l"(c)); return r;
}
static __device__ __forceinline__ ull mul2_(ull a, ull b) {
    ull r; asm("mul.rn.f32x2 %0,%1,%2;" : "=l"(r) : "l"(a), "l"(b)); return r;
}
static __device__ __forceinline__ ull add2_(ull a, ull b) {
    ull r; asm("add.rn.f32x2 %0,%1,%2;" : "=l"(r) : "l"(a), "l"(b)); return r;
}

static __device__ __forceinline__ float hannf(int t) {
    return 0.5f - 0.5f * __cosf(6.283185307179586f * (float)t * (1.0f / 1024.0f));
}

// smem (floats): acc[SPAN] | xs[2][32*34] | tile[2][32*34]
#define XS_F 1088
#define SMEM_FLOATS (SPAN + 4 * XS_F)
#define SMEM_BYTES  (SMEM_FLOATS * 4)

// ---------------------------------------------------------------------------
// Kernel 1: one CTA (64 threads = 2 warps) per 32-frame group.
//   warp0 computes samples [0,640); warp1 starts at 384 with zero state,
//   discards 256 warm-up samples, emits [640,1024). Both accumulate windowed
//   OLA into the shared per-group smem acc (disjoint time ranges, no races).
// ---------------------------------------------------------------------------
__global__ void __launch_bounds__(64)
lpc_ola_kernel(const float* __restrict__ ex,
               const float* __restrict__ gain,
               const float* __restrict__ a,
               float* __restrict__ out) {
    extern __shared__ float smem[];

    const int warp = threadIdx.x >> 5;       // 0 = segA, 1 = segB
    const int lane = threadIdx.x & 31;
    const int gw   = blockIdx.x;              // frame group 0..511
    const int s0   = gw * 32;
    const int s    = s0 + lane;                // this lane's sequence
    const int b    = s >> 10;
    const int ww   = gw & 31;                  // group index within batch
    const int f0   = ww * 32;                  // base frame

    float* __restrict__ acc = smem;
    float* __restrict__ xsw = smem + SPAN + warp * XS_F;
    float* __restrict__ tlw = smem + SPAN + 2 * XS_F + warp * XS_F;

    // zero shared accumulator
    for (int i = threadIdx.x; i < SPAN / 4; i += 64)
        ((float4*)acc)[i] = make_float4(0.f, 0.f, 0.f, 0.f);

    const float g = gain[s];

    // c[q] = -a[q-1] (q=1..22), c[23]=0 ; d[q] = c1*c[q] + c[q+1]
    float c[24];
    #pragma unroll
    for (int p = 0; p < Pn; ++p) c[p + 1] = -a[s * Pn + p];
    c[23] = 0.0f;
    const float c1  = c[1];
    const float c1g = c1 * g;

    ull CA[11], CB[11], H[11];
    #pragma unroll
    for (int k = 0; k < 11; ++k) {
        const float dlo = fmaf(c1, c[2 * k + 1], c[2 * k + 2]);
        const float dhi = fmaf(c1, c[2 * k + 2], c[2 * k + 3]);
        CA[k] = pk2(c[2 * k + 1], c[2 * k + 2]);
        CB[k] = pk2(dlo, dhi);
        H[k]  = 0ull;
    }
    __syncthreads();

    const float* __restrict__ exb = ex + b * Tn;
    const int tbase = warp ? SEGB_T0 : 0;

    // prefetch chunk 0 (coalesced: lane sweeps time, r sweeps frames)
    float xr[32];
    #pragma unroll
    for (int r = 0; r < 32; ++r) {
        int idx = (f0 + r) * HOP + tbase + lane - PADL;
        xr[r] = ((unsigned)idx < (unsigned)Tn) ? exb[idx] : 0.0f;
    }

    for (int cc = 0; cc < NCHUNK; ++cc) {
        const int t0 = tbase + 32 * cc;

        // commit prefetched chunk to this warp's xs
        #pragma unroll
        for (int r = 0; r < 32; ++r) xsw[r * 34 + lane] = xr[r];
        __syncwarp();

        // prefetch next chunk; latency hides under recurrence
        if (cc < NCHUNK - 1) {
            const int t1 = t0 + 32;
            #pragma unroll
            for (int r = 0; r < 32; ++r) {
                int idx = (f0 + r) * HOP + t1 + lane - PADL;
                xr[r] = ((unsigned)idx < (unsigned)Tn) ? exb[idx] : 0.0f;
            }
        }

        // 16 blocks x 2 samples, packed f32x2 dot products vs history
        const float* xrow = xsw + lane * 34;
        float2 xp2 = *(const float2*)xrow;
        #pragma unroll
        for (int bk = 0; bk < 16; ++bk) {
            float2 xn2;
            if (bk < 15) xn2 = *(const float2*)(xrow + 2 * bk + 2);

            const float x0 = xp2.x, x1 = xp2.y;
            const float pre = c1g * x0;

            ull ae = mul2_(CA[10], H[10]);
            ae = fma2_(CA[8], H[8], ae);
            ae = fma2_(CA[6], H[6], ae);
            ae = fma2_(CA[4], H[4], ae);
            ae = fma2_(CA[2], H[2], ae);
            ull ao = mul2_(CA[9], H[9]);
            ao = fma2_(CA[7], H[7], ao);
            ao = fma2_(CA[5], H[5], ao);
            ao = fma2_(CA[3], H[3], ao);
            ao = fma2_(CA[1], H[1], ao);
            ae = fma2_(CA[0], H[0], ae);
            const ull accA = add2_(ae, ao);

            ull be = mul2_(CB[10], H[10]);
            be = fma2_(CB[8], H[8], be);
            be = fma2_(CB[6], H[6], be);
            be = fma2_(CB[4], H[4], be);
            be = fma2_(CB[2], H[2], be);
            ull bo = mul2_(CB[9], H[9]);
            bo = fma2_(CB[7], H[7], bo);
            bo = fma2_(CB[5], H[5], bo);
            bo = fma2_(CB[3], H[3], bo);
            bo = fma2_(CB[1], H[1], bo);
            be = fma2_(CB[0], H[0], be);
            const ull accB = add2_(be, bo);

            float aLo, aHi, bLo, bHi;
            upk2(aLo, aHi, accA);
            upk2(bLo, bHi, accB);

            const float y0 = fmaf(g, x0, aLo + aHi);
            const float y1 = fmaf(g, x1, (bLo + bHi) + pre);

            *(float2*)(tlw + lane * 34 + 2 * bk) = make_float2(y0, y1);

            #pragma unroll
            for (int k = 10; k > 0; --k) H[k] = H[k - 1];
            H[0] = pk2(y1, y0);

            xp2 = xn2;
        }
        __syncwarp();

        // windowed OLA accumulate (skip segB warm-up chunks)
        if (warp == 0 || cc >= WARM_CHUNKS) {
            const float wv = hannf(t0 + lane);
            #pragma unroll
            for (int r = 0; r < 32; ++r)
                acc[r * HOP + t0 + lane] += tlw[r * 34 + lane] * wv;
        }
        __syncwarp();
    }
    __syncthreads();

    // interior [768, 8192): all 4 contributions local; norm == 2 exactly
    float* __restrict__ outb = out + (size_t)b * Tn + ww * 8192 + 384;
    const float4* __restrict__ acc4 = (const float4*)(acc + STRIPL);
    for (int i = threadIdx.x; i < (8192 - STRIPL) / 4; i += 64) {
        float4 v = acc4[i];
        v.x *= 0.5f; v.y *= 0.5f; v.z *= 0.5f; v.w *= 0.5f;
        ((float4*)outb)[i] = v;
    }
    // seams for kernel 2
    for (int j = threadIdx.x; j < STRIPL; j += 64) {
        d_strip_lo[gw][j] = acc[j];
        d_strip_hi[gw][j] = acc[8192 + j];
    }
}

// ---------------------------------------------------------------------------
// Kernel 2: resolve seams. Non-edge seams have norm == 2 exactly; only the
//   batch-leading 768 samples and batch-trailing region need window norms.
// ---------------------------------------------------------------------------
__global__ void strip_kernel(float* __restrict__ out) {
    const int rg = blockIdx.x;
    const int j  = threadIdx.x;        // 0..767

    int w, pbase;
    float sum;
    if (rg < NGRP) {
        w = rg;
        const int ww = w & 31;
        pbase = ww * 8192;
        const int bI = w >> 5;
        if (ww > 0) {                  // interior seam: norm exactly 2
            sum = d_strip_lo[w][j] + d_strip_hi[w - 1][j];
            out[(size_t)bI * Tn + pbase + j - PADL] = sum * 0.5f;
            return;
        }
        sum = d_strip_lo[w][j];        // batch-leading edge
    } else {
        w = ((rg - NGRP) << 5) | 31;   // batch-trailing edge
        pbase = 32 * 8192;
        sum = d_strip_hi[w][j];
    }
    const int bI = w >> 5;
    const int p  = pbase + j;
    const int o  = p - PADL;
    if ((unsigned)o >= (unsigned)Tn) return;

    const int fhi = p >> 8;
    float norm = 0.0f;
    #pragma unroll
    for (int k = 0; k < 4; ++k) {
        const int ff = fhi - k;
        if (ff >= 0 && ff < Fn) norm += hannf(p - ff * HOP);
    }
    out[(size_t)bI * Tn + o] = sum / norm;
}

// ---------------------------------------------------------------------------
extern "C" void kernel_launch(void* const* d_in, const int* in_sizes, int n_in,
                              void* d_out, int out_size) {
    const float* ex   = (const float*)d_in[0];
    const float* gain = (const float*)d_in[1];
    const float* a    = (const float*)d_in[2];
    float* out = (float*)d_out;

    cudaFuncSetAttribute(lpc_ola_kernel,
                         cudaFuncAttributeMaxDynamicSharedMemorySize, SMEM_BYTES);
    lpc_ola_kernel<<<NGRP, 64, SMEM_BYTES>>>(ex, gain, a, out);
    strip_kernel<<<NGRP + Bn, STRIPL>>>(out);
}